// round 13
// baseline (speedup 1.0000x reference)
#include <cuda_runtime.h>
#include <cuda_fp16.h>
#include <math.h>
#include <stdint.h>

// Problem constants
#define BATCH 2
#define SEQ   2048
#define TOK   (BATCH*SEQ)      // 4096 tokens
#define DM    1024
#define EDIM  2048
#define NSTATE 16
#define KCONV 4
#define RRANK 64
#define XDBL  (RRANK + 2*NSTATE)   // 96
#define EPSV  1e-5f
#define NCHUNK 32
#define CLEN   64              // NCHUNK*CLEN = SEQ
#define KSPLIT 4

// ---------------- scratch (device globals, no allocation) ----------------
__device__ float g_xz  [TOK * 2 * EDIM];  // in_proj output (u | z)
__device__ float g_xdbl[TOK * XDBL];      // x_proj output (dt_low|B|C)
__device__ float g_xdp [KSPLIT * TOK * XDBL]; // x_proj split-K partials
__device__ float g_dt  [TOK * EDIM];      // softplus(dt)
__device__ float g_hloc  [BATCH*EDIM*NCHUNK*NSTATE];
__device__ float g_hstart[BATCH*EDIM*NCHUNK*NSTATE];
__device__ float g_ssum  [BATCH*EDIM*NCHUNK];

// fp16 operands
__device__ __half g_xnh[TOK * DM],  g_xnl[TOK * DM];   // rmsnorm out hi/lo
__device__ __half g_wih[2*EDIM*DM];                    // in_proj_w fp16
__device__ __half g_uh [TOK * EDIM], g_ul [TOK * EDIM];// conv out hi/lo
__device__ __half g_xpw[XDBL * EDIM];                  // x_proj_w fp16
__device__ __half g_dtlh[TOK * RRANK], g_dtll[TOK * RRANK]; // dt_low hi/lo
__device__ __half g_dtw[EDIM * RRANK];                 // dt_proj_w fp16
__device__ __half g_yh [TOK * EDIM], g_yl [TOK * EDIM];// scan out hi/lo
__device__ __half g_woh[DM * EDIM];                    // out_proj_w fp16

// ---------------- helpers ----------------
__device__ __forceinline__ uint32_t smem_u32(const void* p) {
    uint32_t a;
    asm("{ .reg .u64 t; cvta.to.shared.u64 t, %1; cvt.u32.u64 %0, t; }" : "=r"(a) : "l"(p));
    return a;
}
__device__ __forceinline__ void ldmx4u(uint32_t* r, uint32_t a) {
    asm volatile("ldmatrix.sync.aligned.m8n8.x4.shared.b16 {%0,%1,%2,%3}, [%4];\n"
                 : "=r"(r[0]), "=r"(r[1]), "=r"(r[2]), "=r"(r[3]) : "r"(a));
}
__device__ __forceinline__ void mma_f16(float* d, const uint32_t* a, const uint32_t* b) {
    asm volatile("mma.sync.aligned.m16n8k16.row.col.f32.f16.f16.f32 "
                 "{%0,%1,%2,%3}, {%4,%5,%6,%7}, {%8,%9}, {%0,%1,%2,%3};\n"
                 : "+f"(d[0]), "+f"(d[1]), "+f"(d[2]), "+f"(d[3])
                 : "r"(a[0]), "r"(a[1]), "r"(a[2]), "r"(a[3]), "r"(b[0]), "r"(b[1]));
}
__device__ __forceinline__ void cpa16u(uint32_t dst, const void* src) {
    asm volatile("cp.async.cg.shared.global [%0], [%1], 16;\n" :: "r"(dst), "l"(src));
}

// merged fp32 -> fp16 convert for all 4 weight tensors
#define N_W0 (2*EDIM*DM)
#define N_W1 (DM*EDIM)
#define N_W2 (XDBL*EDIM)
#define N_W3 (EDIM*RRANK)
__global__ void cvt_all_kernel(const float* __restrict__ s0, __half* __restrict__ d0,
                               const float* __restrict__ s1, __half* __restrict__ d1,
                               const float* __restrict__ s2, __half* __restrict__ d2,
                               const float* __restrict__ s3, __half* __restrict__ d3) {
    int i = blockIdx.x * blockDim.x + threadIdx.x;
    if (i < N_W0) { d0[i] = __float2half(s0[i]); return; }
    i -= N_W0;
    if (i < N_W1) { d1[i] = __float2half(s1[i]); return; }
    i -= N_W1;
    if (i < N_W2) { d2[i] = __float2half(s2[i]); return; }
    i -= N_W2;
    if (i < N_W3) { d3[i] = __float2half(s3[i]); }
}

// ---------------- RMSNorm fused with fp16 hi/lo split ----------------
__global__ void rmsnorm_split_kernel(const float* __restrict__ x,
                                     const float* __restrict__ nw,
                                     __half* __restrict__ xnh,
                                     __half* __restrict__ xnl) {
    int t = blockIdx.x;
    const float* row = x + (size_t)t * DM;
    float ss = 0.f;
    for (int i = threadIdx.x; i < DM; i += 256) {
        float v = row[i];
        ss += v * v;
    }
    for (int o = 16; o > 0; o >>= 1) ss += __shfl_xor_sync(0xffffffffu, ss, o);
    __shared__ float sred[8];
    int wid = threadIdx.x >> 5, lid = threadIdx.x & 31;
    if (lid == 0) sred[wid] = ss;
    __syncthreads();
    __shared__ float s_scale;
    if (threadIdx.x == 0) {
        float tot = 0.f;
        #pragma unroll
        for (int i = 0; i < 8; i++) tot += sred[i];
        s_scale = rsqrtf(tot / (float)DM + EPSV);
    }
    __syncthreads();
    float sc = s_scale;
    for (int i = threadIdx.x; i < DM; i += 256) {
        float v = row[i] * sc * nw[i];
        __half h = __float2half(v);
        xnh[(size_t)t * DM + i] = h;
        xnl[(size_t)t * DM + i] = __float2half(v - __half2float(h));
    }
}

#define ROWB 48
#define ABUF (128*ROWB)
#define NSTAGE 6

// ---------------- generalized fp16 2-term GEMM, 6-stage lookahead-4 ------
// C[M,N] = A[M,K]*B[N,K]^T, A ~ Ah+Al fp16, B ~ Bh fp16.
// Block 128 x (WN*32), 2*WN warps, warp tile 64x32, BK=16.
// EPI: 0 plain | 1 softplus(acc+bias[n]) | 2 +resid | 4 split-K partial
template<int WN, int EPI>
__global__ void __launch_bounds__(WN*64, 2)
gemm_f16x2(const __half* __restrict__ Ah, const __half* __restrict__ Al,
           const __half* __restrict__ Bh,
           float* __restrict__ C, int Kd, int lda, int ldc,
           const float* __restrict__ bias, const float* __restrict__ resid) {
    constexpr int BN = WN * 32;
    constexpr int BBUF = BN * ROWB;
    constexpr int STAGE = 2 * ABUF + BBUF;
    constexpr int THREADS = WN * 64;
    constexpr int ACH = 512;
    constexpr int TOT = ACH + BN * 2;

    extern __shared__ char dsm[];
    const uint32_t dbase = smem_u32(dsm);
    const int tid = threadIdx.x;
    const int lane = tid & 31, warp = tid >> 5;
    const int wm = warp / WN, wn = warp % WN;
    const int m0 = blockIdx.y * 128, n0 = blockIdx.x * BN;
    const int koff = (EPI == 4) ? blockIdx.z * Kd : 0;
    if (EPI == 4) C += (size_t)blockIdx.z * TOK * XDBL;

    const __half* srcA[2] = {Ah + (size_t)m0 * lda + koff,
                             Al + (size_t)m0 * lda + koff};
    const __half* srcB = Bh + (size_t)n0 * lda + koff;

    float acc[4][4][4];
    #pragma unroll
    for (int i = 0; i < 4; i++)
        #pragma unroll
        for (int j = 0; j < 4; j++)
            #pragma unroll
            for (int r = 0; r < 4; r++) acc[i][j][r] = 0.f;

    auto issue = [&](int k0, int st) {
        uint32_t sb = dbase + st * STAGE;
        #pragma unroll
        for (int idx = tid; idx < TOT; idx += THREADS) {
            if (idx < ACH) {
                int buf = idx >> 8;
                int i = idx & 255;
                cpa16u(sb + buf * ABUF + (i >> 1) * ROWB + (i & 1) * 16,
                       srcA[buf] + (size_t)(i >> 1) * lda + k0 + (i & 1) * 8);
            } else {
                int i = idx - ACH;
                cpa16u(sb + 2 * ABUF + (i >> 1) * ROWB + (i & 1) * 16,
                       srcB + (size_t)(i >> 1) * lda + k0 + (i & 1) * 8);
            }
        }
        asm volatile("cp.async.commit_group;\n");
    };

    const int KT = Kd >> 4;
    issue(0, 0);
    issue(16, 1);
    issue(32, 2);
    issue(48, 3);

    const uint32_t a_off = (uint32_t)((wm * 64 + (lane & 15)) * ROWB + (lane >> 4) * 16);
    const uint32_t b_off = (uint32_t)((wn * 32 + (lane & 7) + 8 * (lane >> 4)) * ROWB
                                      + ((lane >> 3) & 1) * 16);

    int st_r = 0, st_w = 4;
    for (int kt = 0; kt < KT; kt++) {
        if (kt + 4 < KT) {
            issue((kt + 4) << 4, st_w);
            asm volatile("cp.async.wait_group 4;\n");
        } else if (kt + 3 < KT) {
            asm volatile("cp.async.wait_group 3;\n");
        } else if (kt + 2 < KT) {
            asm volatile("cp.async.wait_group 2;\n");
        } else if (kt + 1 < KT) {
            asm volatile("cp.async.wait_group 1;\n");
        } else {
            asm volatile("cp.async.wait_group 0;\n");
        }
        __syncthreads();

        uint32_t sb = dbase + st_r * STAGE;
        uint32_t ah[4][4], al[4][4], bh[4][2];
        #pragma unroll
        for (int mt = 0; mt < 4; mt++) {
            ldmx4u(ah[mt], sb + a_off + mt * 16 * ROWB);
            ldmx4u(al[mt], sb + ABUF + a_off + mt * 16 * ROWB);
        }
        #pragma unroll
        for (int np = 0; np < 2; np++) {
            uint32_t t[4];
            ldmx4u(t, sb + 2 * ABUF + b_off + np * 16 * ROWB);
            bh[2*np][0] = t[0]; bh[2*np][1] = t[1];
            bh[2*np+1][0] = t[2]; bh[2*np+1][1] = t[3];
        }
        #pragma unroll
        for (int mt = 0; mt < 4; mt++)
            #pragma unroll
            for (int nt = 0; nt < 4; nt++) {
                mma_f16(acc[mt][nt], ah[mt], bh[nt]);
                mma_f16(acc[mt][nt], al[mt], bh[nt]);
            }
        st_r = (st_r == NSTAGE - 1) ? 0 : st_r + 1;
        st_w = (st_w == NSTAGE - 1) ? 0 : st_w + 1;
    }

    const int gr = lane >> 2, gc2 = (lane & 3) * 2;
    #pragma unroll
    for (int mt = 0; mt < 4; mt++) {
        int m = m0 + wm * 64 + mt * 16 + gr;
        #pragma unroll
        for (int nt = 0; nt < 4; nt++) {
            int n = n0 + wn * 32 + nt * 8 + gc2;
            #pragma unroll
            for (int half = 0; half < 2; half++) {
                int mm = m + half * 8;
                float v0 = acc[mt][nt][half*2+0];
                float v1 = acc[mt][nt][half*2+1];
                if (EPI == 1) {
                    v0 += bias[n];   v0 = (v0 > 20.f) ? v0 : log1pf(__expf(v0));
                    v1 += bias[n+1]; v1 = (v1 > 20.f) ? v1 : log1pf(__expf(v1));
                } else if (EPI == 2) {
                    const float2 rv = *(const float2*)&resid[(size_t)mm * ldc + n];
                    v0 += rv.x; v1 += rv.y;
                }
                *(float2*)&C[(size_t)mm * ldc + n] = make_float2(v0, v1);
            }
        }
    }
}

// ---------------- split-K reduce + dt_low fp16 split ----------------
__global__ void reduce_xdbl_kernel(const float* __restrict__ xdp,
                                   float* __restrict__ xdbl,
                                   __half* __restrict__ dtlh,
                                   __half* __restrict__ dtll) {
    int i = blockIdx.x * 256 + threadIdx.x;
    if (i >= TOK * XDBL) return;
    const int n = TOK * XDBL;
    float s = xdp[i] + xdp[n + i] + xdp[2*n + i] + xdp[3*n + i];
    xdbl[i] = s;
    int col = i % XDBL;
    if (col < RRANK) {
        int row = i / XDBL;
        __half h = __float2half(s);
        dtlh[(size_t)row * RRANK + col] = h;
        dtll[(size_t)row * RRANK + col] = __float2half(s - __half2float(h));
    }
}

// ---------------- causal depthwise conv (K=4) + SiLU -> fp16 pair --------
// vectorized: thread handles 4 consecutive e
__global__ void conv_silu_kernel(const float* __restrict__ xz,
                                 const float* __restrict__ w,
                                 const float* __restrict__ bias,
                                 __half* __restrict__ uh,
                                 __half* __restrict__ ul) {
    int idx4 = blockIdx.x * blockDim.x + threadIdx.x;  // (t*EDIM + e)/4
    if (idx4 >= TOK * EDIM / 4) return;
    int e4 = (idx4 & (EDIM/4 - 1)) * 4;
    int t = idx4 >> 9;
    int b = t >> 11;
    int l = t & (SEQ - 1);
    float4 acc = *(const float4*)&bias[e4];
    #pragma unroll
    for (int j = 0; j < KCONV; j++) {
        int ll = l - (KCONV - 1) + j;
        if (ll >= 0) {
            float4 xv = *(const float4*)&xz[(size_t)(b * SEQ + ll) * (2 * EDIM) + e4];
            acc.x = fmaf(xv.x, w[(e4+0) * KCONV + j], acc.x);
            acc.y = fmaf(xv.y, w[(e4+1) * KCONV + j], acc.y);
            acc.z = fmaf(xv.z, w[(e4+2) * KCONV + j], acc.z);
            acc.w = fmaf(xv.w, w[(e4+3) * KCONV + j], acc.w);
        }
    }
    float v0 = acc.x / (1.f + __expf(-acc.x));
    float v1 = acc.y / (1.f + __expf(-acc.y));
    float v2 = acc.z / (1.f + __expf(-acc.z));
    float v3 = acc.w / (1.f + __expf(-acc.w));
    __half h0 = __float2half(v0), h1 = __float2half(v1);
    __half h2 = __float2half(v2), h3 = __float2half(v3);
    size_t o = (size_t)t * EDIM + e4;
    *(__half2*)&uh[o]     = __halves2half2(h0, h1);
    *(__half2*)&uh[o + 2] = __halves2half2(h2, h3);
    *(__half2*)&ul[o]     = __halves2half2(__float2half(v0 - __half2float(h0)),
                                           __float2half(v1 - __half2float(h1)));
    *(__half2*)&ul[o + 2] = __halves2half2(__float2half(v2 - __half2float(h2)),
                                           __float2half(v3 - __half2float(h3)));
}

// ---------------- chunked selective scan, thread-per-(b,c,e) --------------
__global__ void __launch_bounds__(256) scan_pass1(
        const float* __restrict__ dt,
        const __half* __restrict__ uh,
        const __half* __restrict__ ul,
        const float* __restrict__ xdbl,
        const float* __restrict__ A_log,
        float* __restrict__ hloc,
        float* __restrict__ ssum) {
    const int e = blockIdx.x * 256 + threadIdx.x;
    const int c = blockIdx.y, b = blockIdx.z;
    __shared__ float4 sB[CLEN][NSTATE/4];
    const int t0 = b * SEQ + c * CLEN;
    for (int i = threadIdx.x; i < CLEN * NSTATE / 4; i += 256) {
        int l = i / (NSTATE/4), q = i % (NSTATE/4);
        sB[l][q] = *(const float4*)&xdbl[(size_t)(t0 + l) * XDBL + RRANK + q * 4];
    }
    __syncthreads();
    float Aen[NSTATE];
    #pragma unroll
    for (int q = 0; q < 4; q++) {
        float4 a = *(const float4*)&A_log[e * NSTATE + q * 4];
        Aen[q*4+0] = -__expf(a.x); Aen[q*4+1] = -__expf(a.y);
        Aen[q*4+2] = -__expf(a.z); Aen[q*4+3] = -__expf(a.w);
    }
    float h[NSTATE];
    #pragma unroll
    for (int n = 0; n < NSTATE; n++) h[n] = 0.f;
    float s = 0.f;
    for (int l = 0; l < CLEN; l++) {
        int t = t0 + l;
        size_t idx = (size_t)t * EDIM + e;
        float dtv = dt[idx];
        float uv  = __half2float(uh[idx]) + __half2float(ul[idx]);
        s += dtv;
        float du = dtv * uv;
        #pragma unroll
        for (int q = 0; q < 4; q++) {
            float4 Bv = sB[l][q];
            h[q*4+0] = fmaf(h[q*4+0], __expf(dtv * Aen[q*4+0]), du * Bv.x);
            h[q*4+1] = fmaf(h[q*4+1], __expf(dtv * Aen[q*4+1]), du * Bv.y);
            h[q*4+2] = fmaf(h[q*4+2], __expf(dtv * Aen[q*4+2]), du * Bv.z);
            h[q*4+3] = fmaf(h[q*4+3], __expf(dtv * Aen[q*4+3]), du * Bv.w);
        }
    }
    size_t g = ((size_t)(b * EDIM + e) * NCHUNK + c);
    #pragma unroll
    for (int q = 0; q < 4; q++)
        *(float4*)&hloc[g * NSTATE + q * 4] =
            make_float4(h[q*4+0], h[q*4+1], h[q*4+2], h[q*4+3]);
    ssum[g] = s;
}

__global__ void scan_pass2(const float* __restrict__ A_log,
                           const float* __restrict__ ssum,
                           const float* __restrict__ hloc,
                           float* __restrict__ hstart) {
    int i = blockIdx.x * 256 + threadIdx.x;
    int n = i & 15;
    int e = (i >> 4) & (EDIM - 1);
    int b = i >> 15;
    float Aen = -__expf(A_log[e * NSTATE + n]);
    float h = 0.f;
    int gbase = (b * EDIM + e) * NCHUNK;
    for (int c = 0; c < NCHUNK; c++) {
        int g = gbase + c;
        hstart[(size_t)g * NSTATE + n] = h;
        h = fmaf(h, __expf(Aen * ssum[g]), hloc[(size_t)g * NSTATE + n]);
    }
}

__global__ void __launch_bounds__(256) scan_pass3(
        const float* __restrict__ dt,
        const __half* __restrict__ uh,
        const __half* __restrict__ ul,
        const float* __restrict__ xz,
        const float* __restrict__ xdbl,
        const float* __restrict__ A_log,
        const float* __restrict__ Dp,
        const float* __restrict__ hstart,
        __half* __restrict__ yh,
        __half* __restrict__ yl) {
    const int e = blockIdx.x * 256 + threadIdx.x;
    const int c = blockIdx.y, b = blockIdx.z;
    __shared__ float4 sB[CLEN][NSTATE/4];
    __shared__ float4 sC[CLEN][NSTATE/4];
    const int t0 = b * SEQ + c * CLEN;
    for (int i = threadIdx.x; i < CLEN * NSTATE / 4; i += 256) {
        int l = i / (NSTATE/4), q = i % (NSTATE/4);
        sB[l][q] = *(const float4*)&xdbl[(size_t)(t0 + l) * XDBL + RRANK + q * 4];
        sC[l][q] = *(const float4*)&xdbl[(size_t)(t0 + l) * XDBL + RRANK + NSTATE + q * 4];
    }
    __syncthreads();
    float Aen[NSTATE];
    #pragma unroll
    for (int q = 0; q < 4; q++) {
        float4 a = *(const float4*)&A_log[e * NSTATE + q * 4];
        Aen[q*4+0] = -__expf(a.x); Aen[q*4+1] = -__expf(a.y);
        Aen[q*4+2] = -__expf(a.z); Aen[q*4+3] = -__expf(a.w);
    }
    const float Dv = Dp[e];
    size_t g = ((size_t)(b * EDIM + e) * NCHUNK + c);
    float h[NSTATE];
    #pragma unroll
    for (int q = 0; q < 4; q++) {
        float4 v = *(const float4*)&hstart[g * NSTATE + q * 4];
        h[q*4+0] = v.x; h[q*4+1] = v.y; h[q*4+2] = v.z; h[q*4+3] = v.w;
    }
    for (int l = 0; l < CLEN; l++) {
        int t = t0 + l;
        size_t idx = (size_t)t * EDIM + e;
        float dtv = dt[idx];
        float uv  = __half2float(uh[idx]) + __half2float(ul[idx]);
        float du = dtv * uv;
        float p = 0.f;
        #pragma unroll
        for (int q = 0; q < 4; q++) {
            float4 Bv = sB[l][q];
            float4 Cv = sC[l][q];
            h[q*4+0] = fmaf(h[q*4+0], __expf(dtv * Aen[q*4+0]), du * Bv.x);
            h[q*4+1] = fmaf(h[q*4+1], __expf(dtv * Aen[q*4+1]), du * Bv.y);
            h[q*4+2] = fmaf(h[q*4+2], __expf(dtv * Aen[q*4+2]), du * Bv.z);
            h[q*4+3] = fmaf(h[q*4+3], __expf(dtv * Aen[q*4+3]), du * Bv.w);
            p = fmaf(h[q*4+0], Cv.x, p);
            p = fmaf(h[q*4+1], Cv.y, p);
            p = fmaf(h[q*4+2], Cv.z, p);
            p = fmaf(h[q*4+3], Cv.w, p);
        }
        float zv = xz[(size_t)t * (2 * EDIM) + EDIM + e];
        float sz = zv / (1.f + __expf(-zv));
        float yv = (p + uv * Dv) * sz;
        __half hb = __float2half(yv);
        yh[idx] = hb;
        yl[idx] = __float2half(yv - __half2float(hb));
    }
}

// ---------------- launch ----------------
extern "C" void kernel_launch(void* const* d_in, const int* in_sizes, int n_in,
                              void* d_out, int out_size) {
    const float* x         = (const float*)d_in[0];
    const float* norm_w    = (const float*)d_in[1];
    const float* in_proj_w = (const float*)d_in[2];
    const float* conv_w    = (const float*)d_in[3];
    const float* conv_b    = (const float*)d_in[4];
    const float* x_proj_w  = (const float*)d_in[5];
    const float* dt_proj_w = (const float*)d_in[6];
    const float* dt_proj_b = (const float*)d_in[7];
    const float* A_log     = (const float*)d_in[8];
    const float* Dp        = (const float*)d_in[9];
    const float* out_proj_w= (const float*)d_in[10];
    float* out = (float*)d_out;

    float *p_xz, *p_xdbl, *p_xdp, *p_dt, *p_hloc, *p_hstart, *p_ssum;
    cudaGetSymbolAddress((void**)&p_xz,    g_xz);
    cudaGetSymbolAddress((void**)&p_xdbl,  g_xdbl);
    cudaGetSymbolAddress((void**)&p_xdp,   g_xdp);
    cudaGetSymbolAddress((void**)&p_dt,    g_dt);
    cudaGetSymbolAddress((void**)&p_hloc,  g_hloc);
    cudaGetSymbolAddress((void**)&p_hstart,g_hstart);
    cudaGetSymbolAddress((void**)&p_ssum,  g_ssum);
    __half *p_xnh, *p_xnl, *p_wih, *p_uh, *p_ul, *p_xpw;
    __half *p_dtlh, *p_dtll, *p_dtw, *p_yh, *p_yl, *p_woh;
    cudaGetSymbolAddress((void**)&p_xnh,  g_xnh);
    cudaGetSymbolAddress((void**)&p_xnl,  g_xnl);
    cudaGetSymbolAddress((void**)&p_wih,  g_wih);
    cudaGetSymbolAddress((void**)&p_uh,   g_uh);
    cudaGetSymbolAddress((void**)&p_ul,   g_ul);
    cudaGetSymbolAddress((void**)&p_xpw,  g_xpw);
    cudaGetSymbolAddress((void**)&p_dtlh, g_dtlh);
    cudaGetSymbolAddress((void**)&p_dtll, g_dtll);
    cudaGetSymbolAddress((void**)&p_dtw,  g_dtw);
    cudaGetSymbolAddress((void**)&p_yh,   g_yh);
    cudaGetSymbolAddress((void**)&p_yl,   g_yl);
    cudaGetSymbolAddress((void**)&p_woh,  g_woh);

    const int SMEM_128 = NSTAGE * (2*ABUF + 128*ROWB);  // 110592
    const int SMEM_96  = NSTAGE * (2*ABUF + 96*ROWB);   // 101376
    cudaFuncSetAttribute(gemm_f16x2<4,0>, cudaFuncAttributeMaxDynamicSharedMemorySize, SMEM_128);
    cudaFuncSetAttribute(gemm_f16x2<4,1>, cudaFuncAttributeMaxDynamicSharedMemorySize, SMEM_128);
    cudaFuncSetAttribute(gemm_f16x2<4,2>, cudaFuncAttributeMaxDynamicSharedMemorySize, SMEM_128);
    cudaFuncSetAttribute(gemm_f16x2<3,4>, cudaFuncAttributeMaxDynamicSharedMemorySize, SMEM_96);

    // 1. RMSNorm fused with fp16 split
    rmsnorm_split_kernel<<<TOK, 256>>>(x, norm_w, p_xnh, p_xnl);

    // 2. merged weight converts
    const int NW = N_W0 + N_W1 + N_W2 + N_W3;
    cvt_all_kernel<<<(NW + 255)/256, 256>>>(in_proj_w, p_wih, out_proj_w, p_woh,
                                            x_proj_w, p_xpw, dt_proj_w, p_dtw);

    // 3. in_proj: [4096,1024] -> [4096,4096]
    gemm_f16x2<4,0><<<dim3(2*EDIM/128, TOK/128), 256, SMEM_128>>>(
        p_xnh, p_xnl, p_wih, p_xz, DM, DM, 2*EDIM, nullptr, nullptr);

    // 4. conv + SiLU -> fp16 pair (vectorized)
    conv_silu_kernel<<<(TOK*EDIM/4)/256, 256>>>(p_xz, conv_w, conv_b, p_uh, p_ul);

    // 5. x_proj split-K: 4 x [4096,96,512] partials
    gemm_f16x2<3,4><<<dim3(1, TOK/128, KSPLIT), 192, SMEM_96>>>(
        p_uh, p_ul, p_xpw, p_xdp, EDIM/KSPLIT, EDIM, XDBL, nullptr, nullptr);

    // 5b. reduce partials + dt_low fp16 split
    reduce_xdbl_kernel<<<(TOK*XDBL + 255)/256, 256>>>(p_xdp, p_xdbl, p_dtlh, p_dtll);

    // 6. dt_proj + bias + softplus: [4096,64] @ [2048,64]^T -> [4096,2048]
    gemm_f16x2<4,1><<<dim3(EDIM/128, TOK/128), 256, SMEM_128>>>(
        p_dtlh, p_dtll, p_dtw, p_dt, RRANK, RRANK, EDIM, dt_proj_b, nullptr);

    // 7-9. chunked selective scan (+ D skip + z gate + fp16 split)
    scan_pass1<<<dim3(EDIM/256, NCHUNK, BATCH), 256>>>(
        p_dt, p_uh, p_ul, p_xdbl, A_log, p_hloc, p_ssum);
    scan_pass2<<<BATCH*EDIM*NSTATE/256, 256>>>(A_log, p_ssum, p_hloc, p_hstart);
    scan_pass3<<<dim3(EDIM/256, NCHUNK, BATCH), 256>>>(
        p_dt, p_uh, p_ul, p_xz, p_xdbl, A_log, Dp, p_hstart, p_yh, p_yl);

    // 10. out_proj + residual
    gemm_f16x2<4,2><<<dim3(DM/128, TOK/128), 256, SMEM_128>>>(
        p_yh, p_yl, p_woh, out, EDIM, EDIM, DM, nullptr, x);
}

// round 14
// speedup vs baseline: 1.0429x; 1.0429x over previous
#include <cuda_runtime.h>
#include <cuda_fp16.h>
#include <math.h>
#include <stdint.h>

// Problem constants
#define BATCH 2
#define SEQ   2048
#define TOK   (BATCH*SEQ)      // 4096 tokens
#define DM    1024
#define EDIM  2048
#define NSTATE 16
#define KCONV 4
#define RRANK 64
#define XDBL  (RRANK + 2*NSTATE)   // 96
#define EPSV  1e-5f
#define NCHUNK 32
#define CLEN   64              // NCHUNK*CLEN = SEQ
#define KSPLIT 4

// ---------------- scratch (device globals, no allocation) ----------------
__device__ float g_xz  [TOK * 2 * EDIM];  // in_proj output (u | z)
__device__ float g_xdbl[TOK * XDBL];      // x_proj output (dt_low|B|C)
__device__ float g_xdp [KSPLIT * TOK * XDBL]; // x_proj split-K partials
__device__ float g_dt  [TOK * EDIM];      // softplus(dt)
__device__ float g_hloc  [BATCH*EDIM*NCHUNK*NSTATE];
__device__ float g_hstart[BATCH*EDIM*NCHUNK*NSTATE];
__device__ float g_ssum  [BATCH*EDIM*NCHUNK];

// fp16 operands
__device__ __half g_xnh[TOK * DM],  g_xnl[TOK * DM];   // rmsnorm out hi/lo
__device__ __half g_wih[2*EDIM*DM];                    // in_proj_w fp16
__device__ __half g_uh [TOK * EDIM], g_ul [TOK * EDIM];// conv out hi/lo
__device__ __half g_xpw[XDBL * EDIM];                  // x_proj_w fp16
__device__ __half g_dtlh[TOK * RRANK], g_dtll[TOK * RRANK]; // dt_low hi/lo
__device__ __half g_dtw[EDIM * RRANK];                 // dt_proj_w fp16
__device__ __half g_yh [TOK * EDIM], g_yl [TOK * EDIM];// scan out hi/lo
__device__ __half g_woh[DM * EDIM];                    // out_proj_w fp16

// ---------------- helpers ----------------
__device__ __forceinline__ uint32_t smem_u32(const void* p) {
    uint32_t a;
    asm("{ .reg .u64 t; cvta.to.shared.u64 t, %1; cvt.u32.u64 %0, t; }" : "=r"(a) : "l"(p));
    return a;
}
__device__ __forceinline__ void ldmx4u(uint32_t* r, uint32_t a) {
    asm volatile("ldmatrix.sync.aligned.m8n8.x4.shared.b16 {%0,%1,%2,%3}, [%4];\n"
                 : "=r"(r[0]), "=r"(r[1]), "=r"(r[2]), "=r"(r[3]) : "r"(a));
}
__device__ __forceinline__ void mma_f16(float* d, const uint32_t* a, const uint32_t* b) {
    asm volatile("mma.sync.aligned.m16n8k16.row.col.f32.f16.f16.f32 "
                 "{%0,%1,%2,%3}, {%4,%5,%6,%7}, {%8,%9}, {%0,%1,%2,%3};\n"
                 : "+f"(d[0]), "+f"(d[1]), "+f"(d[2]), "+f"(d[3])
                 : "r"(a[0]), "r"(a[1]), "r"(a[2]), "r"(a[3]), "r"(b[0]), "r"(b[1]));
}
__device__ __forceinline__ void cpa16u(uint32_t dst, const void* src) {
    asm volatile("cp.async.cg.shared.global [%0], [%1], 16;\n" :: "r"(dst), "l"(src));
}

// merged fp32 -> fp16 convert for all 4 weight tensors
#define N_W0 (2*EDIM*DM)
#define N_W1 (DM*EDIM)
#define N_W2 (XDBL*EDIM)
#define N_W3 (EDIM*RRANK)
__global__ void cvt_all_kernel(const float* __restrict__ s0, __half* __restrict__ d0,
                               const float* __restrict__ s1, __half* __restrict__ d1,
                               const float* __restrict__ s2, __half* __restrict__ d2,
                               const float* __restrict__ s3, __half* __restrict__ d3) {
    int i = blockIdx.x * blockDim.x + threadIdx.x;
    if (i < N_W0) { d0[i] = __float2half(s0[i]); return; }
    i -= N_W0;
    if (i < N_W1) { d1[i] = __float2half(s1[i]); return; }
    i -= N_W1;
    if (i < N_W2) { d2[i] = __float2half(s2[i]); return; }
    i -= N_W2;
    if (i < N_W3) { d3[i] = __float2half(s3[i]); }
}

// ---------------- RMSNorm fused with fp16 hi/lo split ----------------
__global__ void rmsnorm_split_kernel(const float* __restrict__ x,
                                     const float* __restrict__ nw,
                                     __half* __restrict__ xnh,
                                     __half* __restrict__ xnl) {
    int t = blockIdx.x;
    const float* row = x + (size_t)t * DM;
    float ss = 0.f;
    for (int i = threadIdx.x; i < DM; i += 256) {
        float v = row[i];
        ss += v * v;
    }
    for (int o = 16; o > 0; o >>= 1) ss += __shfl_xor_sync(0xffffffffu, ss, o);
    __shared__ float sred[8];
    int wid = threadIdx.x >> 5, lid = threadIdx.x & 31;
    if (lid == 0) sred[wid] = ss;
    __syncthreads();
    __shared__ float s_scale;
    if (threadIdx.x == 0) {
        float tot = 0.f;
        #pragma unroll
        for (int i = 0; i < 8; i++) tot += sred[i];
        s_scale = rsqrtf(tot / (float)DM + EPSV);
    }
    __syncthreads();
    float sc = s_scale;
    for (int i = threadIdx.x; i < DM; i += 256) {
        float v = row[i] * sc * nw[i];
        __half h = __float2half(v);
        xnh[(size_t)t * DM + i] = h;
        xnl[(size_t)t * DM + i] = __float2half(v - __half2float(h));
    }
}

#define ROWB 48
#define ABUF (128*ROWB)
#define NSTAGE 5

// ---------------- generalized fp16 2-term GEMM, 5-stage lookahead-3 ------
// C[M,N] = A[M,K]*B[N,K]^T, A ~ Ah+Al fp16, B ~ Bh fp16.
// Block 128 x (WN*32), 2*WN warps, warp tile 64x32, BK=16.
// EPI: 0 plain | 1 softplus(acc+bias[n]) | 2 +resid | 4 split-K partial
template<int WN, int EPI>
__global__ void __launch_bounds__(WN*64, 2)
gemm_f16x2(const __half* __restrict__ Ah, const __half* __restrict__ Al,
           const __half* __restrict__ Bh,
           float* __restrict__ C, int Kd, int lda, int ldc,
           const float* __restrict__ bias, const float* __restrict__ resid) {
    constexpr int BN = WN * 32;
    constexpr int BBUF = BN * ROWB;
    constexpr int STAGE = 2 * ABUF + BBUF;
    constexpr int THREADS = WN * 64;
    constexpr int ACH = 512;
    constexpr int TOT = ACH + BN * 2;

    extern __shared__ char dsm[];
    const uint32_t dbase = smem_u32(dsm);
    const int tid = threadIdx.x;
    const int lane = tid & 31, warp = tid >> 5;
    const int wm = warp / WN, wn = warp % WN;
    const int m0 = blockIdx.y * 128, n0 = blockIdx.x * BN;
    const int koff = (EPI == 4) ? blockIdx.z * Kd : 0;
    if (EPI == 4) C += (size_t)blockIdx.z * TOK * XDBL;

    const __half* srcA[2] = {Ah + (size_t)m0 * lda + koff,
                             Al + (size_t)m0 * lda + koff};
    const __half* srcB = Bh + (size_t)n0 * lda + koff;

    float acc[4][4][4];
    #pragma unroll
    for (int i = 0; i < 4; i++)
        #pragma unroll
        for (int j = 0; j < 4; j++)
            #pragma unroll
            for (int r = 0; r < 4; r++) acc[i][j][r] = 0.f;

    auto issue = [&](int k0, int st) {
        uint32_t sb = dbase + st * STAGE;
        #pragma unroll
        for (int idx = tid; idx < TOT; idx += THREADS) {
            if (idx < ACH) {
                int buf = idx >> 8;
                int i = idx & 255;
                cpa16u(sb + buf * ABUF + (i >> 1) * ROWB + (i & 1) * 16,
                       srcA[buf] + (size_t)(i >> 1) * lda + k0 + (i & 1) * 8);
            } else {
                int i = idx - ACH;
                cpa16u(sb + 2 * ABUF + (i >> 1) * ROWB + (i & 1) * 16,
                       srcB + (size_t)(i >> 1) * lda + k0 + (i & 1) * 8);
            }
        }
        asm volatile("cp.async.commit_group;\n");
    };

    const int KT = Kd >> 4;
    issue(0, 0);
    issue(16, 1);
    issue(32, 2);

    const uint32_t a_off = (uint32_t)((wm * 64 + (lane & 15)) * ROWB + (lane >> 4) * 16);
    const uint32_t b_off = (uint32_t)((wn * 32 + (lane & 7) + 8 * (lane >> 4)) * ROWB
                                      + ((lane >> 3) & 1) * 16);

    int st_r = 0, st_w = 3;
    for (int kt = 0; kt < KT; kt++) {
        if (kt + 3 < KT) {
            issue((kt + 3) << 4, st_w);
            asm volatile("cp.async.wait_group 3;\n");
        } else if (kt + 2 < KT) {
            asm volatile("cp.async.wait_group 2;\n");
        } else if (kt + 1 < KT) {
            asm volatile("cp.async.wait_group 1;\n");
        } else {
            asm volatile("cp.async.wait_group 0;\n");
        }
        __syncthreads();

        uint32_t sb = dbase + st_r * STAGE;
        uint32_t ah[4][4], al[4][4], bh[4][2];
        #pragma unroll
        for (int mt = 0; mt < 4; mt++) {
            ldmx4u(ah[mt], sb + a_off + mt * 16 * ROWB);
            ldmx4u(al[mt], sb + ABUF + a_off + mt * 16 * ROWB);
        }
        #pragma unroll
        for (int np = 0; np < 2; np++) {
            uint32_t t[4];
            ldmx4u(t, sb + 2 * ABUF + b_off + np * 16 * ROWB);
            bh[2*np][0] = t[0]; bh[2*np][1] = t[1];
            bh[2*np+1][0] = t[2]; bh[2*np+1][1] = t[3];
        }
        #pragma unroll
        for (int mt = 0; mt < 4; mt++)
            #pragma unroll
            for (int nt = 0; nt < 4; nt++) {
                mma_f16(acc[mt][nt], ah[mt], bh[nt]);
                mma_f16(acc[mt][nt], al[mt], bh[nt]);
            }
        st_r = (st_r == NSTAGE - 1) ? 0 : st_r + 1;
        st_w = (st_w == NSTAGE - 1) ? 0 : st_w + 1;
    }

    const int gr = lane >> 2, gc2 = (lane & 3) * 2;
    #pragma unroll
    for (int mt = 0; mt < 4; mt++) {
        int m = m0 + wm * 64 + mt * 16 + gr;
        #pragma unroll
        for (int nt = 0; nt < 4; nt++) {
            int n = n0 + wn * 32 + nt * 8 + gc2;
            #pragma unroll
            for (int half = 0; half < 2; half++) {
                int mm = m + half * 8;
                float v0 = acc[mt][nt][half*2+0];
                float v1 = acc[mt][nt][half*2+1];
                if (EPI == 1) {
                    v0 += bias[n];   v0 = (v0 > 20.f) ? v0 : log1pf(__expf(v0));
                    v1 += bias[n+1]; v1 = (v1 > 20.f) ? v1 : log1pf(__expf(v1));
                } else if (EPI == 2) {
                    const float2 rv = *(const float2*)&resid[(size_t)mm * ldc + n];
                    v0 += rv.x; v1 += rv.y;
                }
                *(float2*)&C[(size_t)mm * ldc + n] = make_float2(v0, v1);
            }
        }
    }
}

// ---------------- split-K reduce + dt_low fp16 split ----------------
__global__ void reduce_xdbl_kernel(const float* __restrict__ xdp,
                                   float* __restrict__ xdbl,
                                   __half* __restrict__ dtlh,
                                   __half* __restrict__ dtll) {
    int i = blockIdx.x * 256 + threadIdx.x;
    if (i >= TOK * XDBL) return;
    const int n = TOK * XDBL;
    float s = xdp[i] + xdp[n + i] + xdp[2*n + i] + xdp[3*n + i];
    xdbl[i] = s;
    int col = i % XDBL;
    if (col < RRANK) {
        int row = i / XDBL;
        __half h = __float2half(s);
        dtlh[(size_t)row * RRANK + col] = h;
        dtll[(size_t)row * RRANK + col] = __float2half(s - __half2float(h));
    }
}

// ---------------- causal depthwise conv (K=4) + SiLU -> fp16 pair --------
// vectorized over 4 consecutive e; weights loaded as 4 contiguous float4
__global__ void conv_silu_kernel(const float* __restrict__ xz,
                                 const float* __restrict__ w,
                                 const float* __restrict__ bias,
                                 __half* __restrict__ uh,
                                 __half* __restrict__ ul) {
    int idx4 = blockIdx.x * blockDim.x + threadIdx.x;  // (t*EDIM + e)/4
    if (idx4 >= TOK * EDIM / 4) return;
    int e4 = (idx4 & (EDIM/4 - 1)) * 4;
    int t = idx4 >> 9;
    int b = t >> 11;
    int l = t & (SEQ - 1);
    // w rows for e4..e4+3 are 16 contiguous floats
    float4 w0 = *(const float4*)&w[(e4+0) * KCONV];
    float4 w1 = *(const float4*)&w[(e4+1) * KCONV];
    float4 w2 = *(const float4*)&w[(e4+2) * KCONV];
    float4 w3 = *(const float4*)&w[(e4+3) * KCONV];
    float4 acc = *(const float4*)&bias[e4];
    #pragma unroll
    for (int j = 0; j < KCONV; j++) {
        int ll = l - (KCONV - 1) + j;
        if (ll >= 0) {
            float4 xv = *(const float4*)&xz[(size_t)(b * SEQ + ll) * (2 * EDIM) + e4];
            float wj0 = (j==0)?w0.x:(j==1)?w0.y:(j==2)?w0.z:w0.w;
            float wj1 = (j==0)?w1.x:(j==1)?w1.y:(j==2)?w1.z:w1.w;
            float wj2 = (j==0)?w2.x:(j==1)?w2.y:(j==2)?w2.z:w2.w;
            float wj3 = (j==0)?w3.x:(j==1)?w3.y:(j==2)?w3.z:w3.w;
            acc.x = fmaf(xv.x, wj0, acc.x);
            acc.y = fmaf(xv.y, wj1, acc.y);
            acc.z = fmaf(xv.z, wj2, acc.z);
            acc.w = fmaf(xv.w, wj3, acc.w);
        }
    }
    float v0 = acc.x / (1.f + __expf(-acc.x));
    float v1 = acc.y / (1.f + __expf(-acc.y));
    float v2 = acc.z / (1.f + __expf(-acc.z));
    float v3 = acc.w / (1.f + __expf(-acc.w));
    __half h0 = __float2half(v0), h1 = __float2half(v1);
    __half h2 = __float2half(v2), h3 = __float2half(v3);
    size_t o = (size_t)t * EDIM + e4;
    *(__half2*)&uh[o]     = __halves2half2(h0, h1);
    *(__half2*)&uh[o + 2] = __halves2half2(h2, h3);
    *(__half2*)&ul[o]     = __halves2half2(__float2half(v0 - __half2float(h0)),
                                           __float2half(v1 - __half2float(h1)));
    *(__half2*)&ul[o + 2] = __halves2half2(__float2half(v2 - __half2float(h2)),
                                           __float2half(v3 - __half2float(h3)));
}

// ---------------- chunked selective scan, thread-per-(b,c,e) --------------
__global__ void __launch_bounds__(256) scan_pass1(
        const float* __restrict__ dt,
        const __half* __restrict__ uh,
        const __half* __restrict__ ul,
        const float* __restrict__ xdbl,
        const float* __restrict__ A_log,
        float* __restrict__ hloc,
        float* __restrict__ ssum) {
    const int e = blockIdx.x * 256 + threadIdx.x;
    const int c = blockIdx.y, b = blockIdx.z;
    __shared__ float4 sB[CLEN][NSTATE/4];
    const int t0 = b * SEQ + c * CLEN;
    for (int i = threadIdx.x; i < CLEN * NSTATE / 4; i += 256) {
        int l = i / (NSTATE/4), q = i % (NSTATE/4);
        sB[l][q] = *(const float4*)&xdbl[(size_t)(t0 + l) * XDBL + RRANK + q * 4];
    }
    __syncthreads();
    float Aen[NSTATE];
    #pragma unroll
    for (int q = 0; q < 4; q++) {
        float4 a = *(const float4*)&A_log[e * NSTATE + q * 4];
        Aen[q*4+0] = -__expf(a.x); Aen[q*4+1] = -__expf(a.y);
        Aen[q*4+2] = -__expf(a.z); Aen[q*4+3] = -__expf(a.w);
    }
    float h[NSTATE];
    #pragma unroll
    for (int n = 0; n < NSTATE; n++) h[n] = 0.f;
    float s = 0.f;
    for (int l = 0; l < CLEN; l++) {
        int t = t0 + l;
        size_t idx = (size_t)t * EDIM + e;
        float dtv = dt[idx];
        float uv  = __half2float(uh[idx]) + __half2float(ul[idx]);
        s += dtv;
        float du = dtv * uv;
        #pragma unroll
        for (int q = 0; q < 4; q++) {
            float4 Bv = sB[l][q];
            h[q*4+0] = fmaf(h[q*4+0], __expf(dtv * Aen[q*4+0]), du * Bv.x);
            h[q*4+1] = fmaf(h[q*4+1], __expf(dtv * Aen[q*4+1]), du * Bv.y);
            h[q*4+2] = fmaf(h[q*4+2], __expf(dtv * Aen[q*4+2]), du * Bv.z);
            h[q*4+3] = fmaf(h[q*4+3], __expf(dtv * Aen[q*4+3]), du * Bv.w);
        }
    }
    size_t g = ((size_t)(b * EDIM + e) * NCHUNK + c);
    #pragma unroll
    for (int q = 0; q < 4; q++)
        *(float4*)&hloc[g * NSTATE + q * 4] =
            make_float4(h[q*4+0], h[q*4+1], h[q*4+2], h[q*4+3]);
    ssum[g] = s;
}

__global__ void scan_pass2(const float* __restrict__ A_log,
                           const float* __restrict__ ssum,
                           const float* __restrict__ hloc,
                           float* __restrict__ hstart) {
    int i = blockIdx.x * 256 + threadIdx.x;
    int n = i & 15;
    int e = (i >> 4) & (EDIM - 1);
    int b = i >> 15;
    float Aen = -__expf(A_log[e * NSTATE + n]);
    float h = 0.f;
    int gbase = (b * EDIM + e) * NCHUNK;
    for (int c = 0; c < NCHUNK; c++) {
        int g = gbase + c;
        hstart[(size_t)g * NSTATE + n] = h;
        h = fmaf(h, __expf(Aen * ssum[g]), hloc[(size_t)g * NSTATE + n]);
    }
}

__global__ void __launch_bounds__(256) scan_pass3(
        const float* __restrict__ dt,
        const __half* __restrict__ uh,
        const __half* __restrict__ ul,
        const float* __restrict__ xz,
        const float* __restrict__ xdbl,
        const float* __restrict__ A_log,
        const float* __restrict__ Dp,
        const float* __restrict__ hstart,
        __half* __restrict__ yh,
        __half* __restrict__ yl) {
    const int e = blockIdx.x * 256 + threadIdx.x;
    const int c = blockIdx.y, b = blockIdx.z;
    __shared__ float4 sB[CLEN][NSTATE/4];
    __shared__ float4 sC[CLEN][NSTATE/4];
    const int t0 = b * SEQ + c * CLEN;
    for (int i = threadIdx.x; i < CLEN * NSTATE / 4; i += 256) {
        int l = i / (NSTATE/4), q = i % (NSTATE/4);
        sB[l][q] = *(const float4*)&xdbl[(size_t)(t0 + l) * XDBL + RRANK + q * 4];
        sC[l][q] = *(const float4*)&xdbl[(size_t)(t0 + l) * XDBL + RRANK + NSTATE + q * 4];
    }
    __syncthreads();
    float Aen[NSTATE];
    #pragma unroll
    for (int q = 0; q < 4; q++) {
        float4 a = *(const float4*)&A_log[e * NSTATE + q * 4];
        Aen[q*4+0] = -__expf(a.x); Aen[q*4+1] = -__expf(a.y);
        Aen[q*4+2] = -__expf(a.z); Aen[q*4+3] = -__expf(a.w);
    }
    const float Dv = Dp[e];
    size_t g = ((size_t)(b * EDIM + e) * NCHUNK + c);
    float h[NSTATE];
    #pragma unroll
    for (int q = 0; q < 4; q++) {
        float4 v = *(const float4*)&hstart[g * NSTATE + q * 4];
        h[q*4+0] = v.x; h[q*4+1] = v.y; h[q*4+2] = v.z; h[q*4+3] = v.w;
    }
    for (int l = 0; l < CLEN; l++) {
        int t = t0 + l;
        size_t idx = (size_t)t * EDIM + e;
        float dtv = dt[idx];
        float uv  = __half2float(uh[idx]) + __half2float(ul[idx]);
        float du = dtv * uv;
        float p = 0.f;
        #pragma unroll
        for (int q = 0; q < 4; q++) {
            float4 Bv = sB[l][q];
            float4 Cv = sC[l][q];
            h[q*4+0] = fmaf(h[q*4+0], __expf(dtv * Aen[q*4+0]), du * Bv.x);
            h[q*4+1] = fmaf(h[q*4+1], __expf(dtv * Aen[q*4+1]), du * Bv.y);
            h[q*4+2] = fmaf(h[q*4+2], __expf(dtv * Aen[q*4+2]), du * Bv.z);
            h[q*4+3] = fmaf(h[q*4+3], __expf(dtv * Aen[q*4+3]), du * Bv.w);
            p = fmaf(h[q*4+0], Cv.x, p);
            p = fmaf(h[q*4+1], Cv.y, p);
            p = fmaf(h[q*4+2], Cv.z, p);
            p = fmaf(h[q*4+3], Cv.w, p);
        }
        float zv = xz[(size_t)t * (2 * EDIM) + EDIM + e];
        float sz = zv / (1.f + __expf(-zv));
        float yv = (p + uv * Dv) * sz;
        __half hb = __float2half(yv);
        yh[idx] = hb;
        yl[idx] = __float2half(yv - __half2float(hb));
    }
}

// ---------------- launch ----------------
extern "C" void kernel_launch(void* const* d_in, const int* in_sizes, int n_in,
                              void* d_out, int out_size) {
    const float* x         = (const float*)d_in[0];
    const float* norm_w    = (const float*)d_in[1];
    const float* in_proj_w = (const float*)d_in[2];
    const float* conv_w    = (const float*)d_in[3];
    const float* conv_b    = (const float*)d_in[4];
    const float* x_proj_w  = (const float*)d_in[5];
    const float* dt_proj_w = (const float*)d_in[6];
    const float* dt_proj_b = (const float*)d_in[7];
    const float* A_log     = (const float*)d_in[8];
    const float* Dp        = (const float*)d_in[9];
    const float* out_proj_w= (const float*)d_in[10];
    float* out = (float*)d_out;

    float *p_xz, *p_xdbl, *p_xdp, *p_dt, *p_hloc, *p_hstart, *p_ssum;
    cudaGetSymbolAddress((void**)&p_xz,    g_xz);
    cudaGetSymbolAddress((void**)&p_xdbl,  g_xdbl);
    cudaGetSymbolAddress((void**)&p_xdp,   g_xdp);
    cudaGetSymbolAddress((void**)&p_dt,    g_dt);
    cudaGetSymbolAddress((void**)&p_hloc,  g_hloc);
    cudaGetSymbolAddress((void**)&p_hstart,g_hstart);
    cudaGetSymbolAddress((void**)&p_ssum,  g_ssum);
    __half *p_xnh, *p_xnl, *p_wih, *p_uh, *p_ul, *p_xpw;
    __half *p_dtlh, *p_dtll, *p_dtw, *p_yh, *p_yl, *p_woh;
    cudaGetSymbolAddress((void**)&p_xnh,  g_xnh);
    cudaGetSymbolAddress((void**)&p_xnl,  g_xnl);
    cudaGetSymbolAddress((void**)&p_wih,  g_wih);
    cudaGetSymbolAddress((void**)&p_uh,   g_uh);
    cudaGetSymbolAddress((void**)&p_ul,   g_ul);
    cudaGetSymbolAddress((void**)&p_xpw,  g_xpw);
    cudaGetSymbolAddress((void**)&p_dtlh, g_dtlh);
    cudaGetSymbolAddress((void**)&p_dtll, g_dtll);
    cudaGetSymbolAddress((void**)&p_dtw,  g_dtw);
    cudaGetSymbolAddress((void**)&p_yh,   g_yh);
    cudaGetSymbolAddress((void**)&p_yl,   g_yl);
    cudaGetSymbolAddress((void**)&p_woh,  g_woh);

    const int SMEM_128 = NSTAGE * (2*ABUF + 128*ROWB);  // 92160
    const int SMEM_96  = NSTAGE * (2*ABUF + 96*ROWB);   // 84480
    cudaFuncSetAttribute(gemm_f16x2<4,0>, cudaFuncAttributeMaxDynamicSharedMemorySize, SMEM_128);
    cudaFuncSetAttribute(gemm_f16x2<4,1>, cudaFuncAttributeMaxDynamicSharedMemorySize, SMEM_128);
    cudaFuncSetAttribute(gemm_f16x2<4,2>, cudaFuncAttributeMaxDynamicSharedMemorySize, SMEM_128);
    cudaFuncSetAttribute(gemm_f16x2<3,4>, cudaFuncAttributeMaxDynamicSharedMemorySize, SMEM_96);

    // 1. RMSNorm fused with fp16 split
    rmsnorm_split_kernel<<<TOK, 256>>>(x, norm_w, p_xnh, p_xnl);

    // 2. merged weight converts
    const int NW = N_W0 + N_W1 + N_W2 + N_W3;
    cvt_all_kernel<<<(NW + 255)/256, 256>>>(in_proj_w, p_wih, out_proj_w, p_woh,
                                            x_proj_w, p_xpw, dt_proj_w, p_dtw);

    // 3. in_proj: [4096,1024] -> [4096,4096]
    gemm_f16x2<4,0><<<dim3(2*EDIM/128, TOK/128), 256, SMEM_128>>>(
        p_xnh, p_xnl, p_wih, p_xz, DM, DM, 2*EDIM, nullptr, nullptr);

    // 4. conv + SiLU -> fp16 pair (vectorized, coalesced weights)
    conv_silu_kernel<<<(TOK*EDIM/4)/256, 256>>>(p_xz, conv_w, conv_b, p_uh, p_ul);

    // 5. x_proj split-K: 4 x [4096,96,512] partials
    gemm_f16x2<3,4><<<dim3(1, TOK/128, KSPLIT), 192, SMEM_96>>>(
        p_uh, p_ul, p_xpw, p_xdp, EDIM/KSPLIT, EDIM, XDBL, nullptr, nullptr);

    // 5b. reduce partials + dt_low fp16 split
    reduce_xdbl_kernel<<<(TOK*XDBL + 255)/256, 256>>>(p_xdp, p_xdbl, p_dtlh, p_dtll);

    // 6. dt_proj + bias + softplus: [4096,64] @ [2048,64]^T -> [4096,2048]
    gemm_f16x2<4,1><<<dim3(EDIM/128, TOK/128), 256, SMEM_128>>>(
        p_dtlh, p_dtll, p_dtw, p_dt, RRANK, RRANK, EDIM, dt_proj_b, nullptr);

    // 7-9. chunked selective scan (+ D skip + z gate + fp16 split)
    scan_pass1<<<dim3(EDIM/256, NCHUNK, BATCH), 256>>>(
        p_dt, p_uh, p_ul, p_xdbl, A_log, p_hloc, p_ssum);
    scan_pass2<<<BATCH*EDIM*NSTATE/256, 256>>>(A_log, p_ssum, p_hloc, p_hstart);
    scan_pass3<<<dim3(EDIM/256, NCHUNK, BATCH), 256>>>(
        p_dt, p_uh, p_ul, p_xz, p_xdbl, A_log, Dp, p_hstart, p_yh, p_yl);

    // 10. out_proj + residual
    gemm_f16x2<4,2><<<dim3(DM/128, TOK/128), 256, SMEM_128>>>(
        p_yh, p_yl, p_woh, out, EDIM, EDIM, DM, nullptr, x);
}